// round 15
// baseline (speedup 1.0000x reference)
#include <cuda_runtime.h>
#include <cuda_bf16.h>

// Problem constants: b=2, s=4096, h=16, p=n=64, BLOCK_LEN=64
#define NB   2
#define NH   16
#define NC   64
#define PB   144   // bf16 tile row pitch in BYTES (72 bf16) -> LDSM conflict-free

// gemm13 smem: 6 tiles (X,B,C split pairs)
#define G1_XH 0
#define G1_XL 9216
#define G1_BH 18432
#define G1_BL 27648
#define G1_CH 36864
#define G1_CL 46080
#define SMEMG1 55296

// pass3 smem: 4 resident tiles (T0: C then X; T1: S then G)
#define P3_T0H 0
#define P3_T0L 9216
#define P3_T1H 18432
#define P3_T1L 27648
#define SMEMP3 36864

// Scratch (__device__ globals; allocation-free rule)
__device__ float    g_states[NB*NH*NC*4096]; // chunk states [p][n]; scanned in place
__device__ unsigned g_Gh[NB*NH*NC*2048];     // G[s][l] hi bf16 pairs
__device__ unsigned g_Gl[NB*NH*NC*2048];     // G[s][l] lo bf16 pairs
__device__ float    g_tot[NB*NH*NC];         // per-chunk A totals

#define MMA_BF16(d, a0, a1, a2, a3, b0, b1)                               \
    asm("mma.sync.aligned.m16n8k16.row.col.f32.bf16.bf16.f32 "            \
        "{%0,%1,%2,%3}, {%4,%5,%6,%7}, {%8,%9}, {%0,%1,%2,%3};"           \
        : "+f"(d[0]), "+f"(d[1]), "+f"(d[2]), "+f"(d[3])                  \
        : "r"(a0), "r"(a1), "r"(a2), "r"(a3), "r"(b0), "r"(b1))

// cheap exact 2-term split: hi = mantissa-truncated bf16 (1 PRMT per pair),
// lo = v - hi rounded to bf16 (2 FSUB + 1 cvt per pair).
__device__ __forceinline__ unsigned pack_hi2(float a, float b) {
    return __byte_perm(__float_as_uint(a), __float_as_uint(b), 0x7632);
}
__device__ __forceinline__ unsigned pack_lo2(float a, float b) {
    const float la = a - __uint_as_float(__float_as_uint(a) & 0xFFFF0000u);
    const float lb = b - __uint_as_float(__float_as_uint(b) & 0xFFFF0000u);
    unsigned r;
    asm("cvt.rn.bf16x2.f32 %0, %1, %2;" : "=r"(r) : "f"(lb), "f"(la));
    return r;
}
__device__ __forceinline__ void split4_store(float4 v, char* hp, char* lp) {
    *(uint2*)(hp) = make_uint2(pack_hi2(v.x, v.y), pack_hi2(v.z, v.w));
    *(uint2*)(lp) = make_uint2(pack_lo2(v.x, v.y), pack_lo2(v.z, v.w));
}

// A-fragment (m16k16) from k-major storage T[k][m] via ldmatrix.trans.
__device__ __forceinline__ void ldsm4_a_trans(
    const char* tile, int kt, int mbase, int lane,
    unsigned& a0, unsigned& a1, unsigned& a2, unsigned& a3)
{
    const int row  = kt*16 + ((lane>>4)<<3) + (lane&7);
    const int colb = (mbase + ((lane>>3)&1)*8)*2;
    unsigned addr = (unsigned)__cvta_generic_to_shared(tile + row*PB + colb);
    asm volatile("ldmatrix.sync.aligned.m8n8.x4.trans.shared.b16 {%0,%1,%2,%3}, [%4];"
                 : "=r"(a0),"=r"(a1),"=r"(a2),"=r"(a3) : "r"(addr));
}
// B-fragments for two consecutive k16 blocks from k-major storage T[k][n].
__device__ __forceinline__ void ldsm4_b_trans(
    const char* tile, int khalf, int nt, int lane,
    unsigned& b0, unsigned& b1, unsigned& b2, unsigned& b3)
{
    unsigned addr = (unsigned)__cvta_generic_to_shared(
        tile + (khalf*32 + lane)*PB + nt*16);
    asm volatile("ldmatrix.sync.aligned.m8n8.x4.trans.shared.b16 {%0,%1,%2,%3}, [%4];"
                 : "=r"(b0),"=r"(b1),"=r"(b2),"=r"(b3) : "r"(addr));
}

// ---------------------------------------------------------------------------
// Kernel A (gemm13): GEMM1 + GEMM3 fused, single sync.
//  GEMM1: D[s][l] = sum_n B[s][n]*C[l][n]; epi: mask l>=s, *em[s] -> g_Gh/g_Gl
//  GEMM3: St[p][n] = sum_l (w[l]*X[l][p])*B[l][n] -> g_states [p][n]
// B used straight in both (manual frags / LDSM.trans).
// ---------------------------------------------------------------------------
__global__ void __launch_bounds__(128, 4) gemm13_kernel(
    const float* __restrict__ X, const float* __restrict__ A,
    const float* __restrict__ B, const float* __restrict__ C)
{
    extern __shared__ char smem[];
    __shared__ float s_cs[64], s_w[64], s_em[64];

    const int c = blockIdx.x, h = blockIdx.y, b = blockIdx.z;
    const int bhc = (b*NH + h)*NC + c;
    const int tid = threadIdx.x;
    const int tx = tid & 15, ty = tid >> 4;
    const size_t base = ((size_t)((b*4096 + c*64)*NH + h))*64;
    const int col4 = tx*4;

    if (tid < 64) {
        const float av = A[(size_t)(b*4096 + c*64 + tid)*NH + h];
        float v = av;
        #pragma unroll
        for (int o = 1; o < 32; o <<= 1) {
            float t = __shfl_up_sync(0xffffffffu, v, o);
            if ((tid & 31) >= o) v += t;
        }
        s_cs[tid] = v;
        s_em[tid] = av;
    }
    __syncthreads();
    if (tid >= 32 && tid < 64) s_cs[tid] += s_cs[31];
    __syncthreads();
    if (tid < 64) {
        const float csl = s_cs[tid], total = s_cs[63];
        s_w[tid]  = __expf(total - csl);
        s_em[tid] = __expf(s_em[tid] - csl);
        if (tid == 63) g_tot[bhc] = total;
    }
    __syncthreads();

    // tile loads: X scaled by w; B, C straight; all split-stored
    #pragma unroll
    for (int i = 0; i < 8; i++) {
        const int row = i*8 + ty;
        const size_t g = base + (size_t)row*1024 + col4;
        float4 xf = *(const float4*)(X + g);
        float4 bf = *(const float4*)(B + g);
        float4 cf = *(const float4*)(C + g);
        const float w = s_w[row];
        xf.x *= w; xf.y *= w; xf.z *= w; xf.w *= w;
        split4_store(xf, smem + G1_XH + row*PB + col4*2,
                         smem + G1_XL + row*PB + col4*2);
        split4_store(bf, smem + G1_BH + row*PB + col4*2,
                         smem + G1_BL + row*PB + col4*2);
        split4_store(cf, smem + G1_CH + row*PB + col4*2,
                         smem + G1_CL + row*PB + col4*2);
    }
    __syncthreads();   // the ONLY sync: both GEMMs only read these tiles

    const int w = tid >> 5, lane = tid & 31;
    const int gq = lane >> 2, t4 = lane & 3;
    const int r0 = 16*w + gq;

    unsigned ah[16], al[16];

    // ---- GEMM1: A=B[s][n] (manual), Bop=C[l][n] (manual) -> accG[s][l] ----
    {
        float accG[8][4];
        #pragma unroll
        for (int nt = 0; nt < 8; nt++)
            #pragma unroll
            for (int j = 0; j < 4; j++) accG[nt][j] = 0.f;

        #pragma unroll
        for (int kt = 0; kt < 4; kt++) {
            const int kb = (kt*16 + 2*t4)*2;
            ah[kt*4+0] = *(const unsigned*)(smem + G1_BH + (r0  )*PB + kb);
            ah[kt*4+1] = *(const unsigned*)(smem + G1_BH + (r0+8)*PB + kb);
            ah[kt*4+2] = *(const unsigned*)(smem + G1_BH + (r0  )*PB + kb + 16);
            ah[kt*4+3] = *(const unsigned*)(smem + G1_BH + (r0+8)*PB + kb + 16);
            al[kt*4+0] = *(const unsigned*)(smem + G1_BL + (r0  )*PB + kb);
            al[kt*4+1] = *(const unsigned*)(smem + G1_BL + (r0+8)*PB + kb);
            al[kt*4+2] = *(const unsigned*)(smem + G1_BL + (r0  )*PB + kb + 16);
            al[kt*4+3] = *(const unsigned*)(smem + G1_BL + (r0+8)*PB + kb + 16);
        }
        #pragma unroll
        for (int nt = 0; nt < 8; nt++) {
            #pragma unroll
            for (int kt = 0; kt < 4; kt++) {
                const int kb = (kt*16 + 2*t4)*2;
                const char* pr = smem + (nt*8 + gq)*PB + kb;
                unsigned bh0 = *(const unsigned*)(pr + G1_CH);
                unsigned bh1 = *(const unsigned*)(pr + G1_CH + 16);
                unsigned bl0 = *(const unsigned*)(pr + G1_CL);
                unsigned bl1 = *(const unsigned*)(pr + G1_CL + 16);
                MMA_BF16(accG[nt], ah[kt*4+0], ah[kt*4+1], ah[kt*4+2], ah[kt*4+3], bh0, bh1);
                MMA_BF16(accG[nt], ah[kt*4+0], ah[kt*4+1], ah[kt*4+2], ah[kt*4+3], bl0, bl1);
                MMA_BF16(accG[nt], al[kt*4+0], al[kt*4+1], al[kt*4+2], al[kt*4+3], bh0, bh1);
            }
        }

        // epilogue: mask + em, split -> global G[s][l] (bf16 pair words)
        const int s0 = r0, s1 = r0 + 8;
        const float em0 = s_em[s0], em1 = s_em[s1];
        unsigned* gh = g_Gh + bhc*2048;
        unsigned* gl = g_Gl + bhc*2048;
        #pragma unroll
        for (int nt = 0; nt < 8; nt++) {
            const int l0 = nt*8 + 2*t4;
            float v00 = (l0   >= s0) ? accG[nt][0]*em0 : 0.f;
            float v01 = (l0+1 >= s0) ? accG[nt][1]*em0 : 0.f;
            float v10 = (l0   >= s1) ? accG[nt][2]*em1 : 0.f;
            float v11 = (l0+1 >= s1) ? accG[nt][3]*em1 : 0.f;
            gh[s0*32 + (l0>>1)] = pack_hi2(v00, v01);
            gl[s0*32 + (l0>>1)] = pack_lo2(v00, v01);
            gh[s1*32 + (l0>>1)] = pack_hi2(v10, v11);
            gl[s1*32 + (l0>>1)] = pack_lo2(v10, v11);
        }
    }

    // ---- GEMM3: A=(wX)^T via LDSM.trans, Bop=B^T via LDSM.trans ----
    {
        #pragma unroll
        for (int kt = 0; kt < 4; kt++) {
            ldsm4_a_trans(smem + G1_XH, kt, 16*w, lane,
                          ah[kt*4+0], ah[kt*4+1], ah[kt*4+2], ah[kt*4+3]);
            ldsm4_a_trans(smem + G1_XL, kt, 16*w, lane,
                          al[kt*4+0], al[kt*4+1], al[kt*4+2], al[kt*4+3]);
        }
        float acc[8][4];
        #pragma unroll
        for (int nt = 0; nt < 8; nt++)
            #pragma unroll
            for (int j = 0; j < 4; j++) acc[nt][j] = 0.f;

        #pragma unroll
        for (int nt = 0; nt < 8; nt++) {
            #pragma unroll
            for (int kh = 0; kh < 2; kh++) {
                unsigned bh0,bh1,bh2,bh3, bl0,bl1,bl2,bl3;
                ldsm4_b_trans(smem + G1_BH, kh, nt, lane, bh0,bh1,bh2,bh3);
                ldsm4_b_trans(smem + G1_BL, kh, nt, lane, bl0,bl1,bl2,bl3);
                const int k0 = (kh*2)*4, k1 = (kh*2+1)*4;
                MMA_BF16(acc[nt], ah[k0+0], ah[k0+1], ah[k0+2], ah[k0+3], bh0, bh1);
                MMA_BF16(acc[nt], ah[k0+0], ah[k0+1], ah[k0+2], ah[k0+3], bl0, bl1);
                MMA_BF16(acc[nt], al[k0+0], al[k0+1], al[k0+2], al[k0+3], bh0, bh1);
                MMA_BF16(acc[nt], ah[k1+0], ah[k1+1], ah[k1+2], ah[k1+3], bh2, bh3);
                MMA_BF16(acc[nt], ah[k1+0], ah[k1+1], ah[k1+2], ah[k1+3], bl2, bl3);
                MMA_BF16(acc[nt], al[k1+0], al[k1+1], al[k1+2], al[k1+3], bh2, bh3);
            }
        }

        float* st = g_states + (size_t)bhc*4096;
        const int p0 = r0, p1 = r0 + 8;
        #pragma unroll
        for (int nt = 0; nt < 8; nt++) {
            const int n0 = nt*8 + 2*t4;
            *(float2*)(st + p0*64 + n0) = make_float2(acc[nt][0], acc[nt][1]);
            *(float2*)(st + p1*64 + n0) = make_float2(acc[nt][2], acc[nt][3]);
        }
    }
}

// ---------------------------------------------------------------------------
// Pass 2: inter-chunk scan, in place (fp32).
// ---------------------------------------------------------------------------
__global__ void __launch_bounds__(128) pass2_kernel()
{
    __shared__ float se[NC];
    const int slice = blockIdx.x, bh = blockIdx.y;
    const int tid = threadIdx.x;

    if (tid < NC) se[tid] = __expf(g_tot[bh*NC + tid]);
    __syncthreads();

    float* p = g_states + (size_t)bh*NC*4096 + slice*512 + tid*4;
    float4 v[8];
    #pragma unroll
    for (int j = 0; j < 8; j++) v[j] = *(float4*)(p + (size_t)j*4096);

    float4 S = make_float4(0.f, 0.f, 0.f, 0.f);
    #pragma unroll 8
    for (int c = 0; c < NC; c++) {
        float4 cur = v[c & 7];
        *(float4*)(p + (size_t)c*4096) = S;
        const float e = se[c];
        S.x = e * (S.x + cur.x);
        S.y = e * (S.y + cur.y);
        S.z = e * (S.z + cur.z);
        S.w = e * (S.w + cur.w);
        if (c + 8 < NC) v[c & 7] = *(float4*)(p + (size_t)(c+8)*4096);
    }
}

// ---------------------------------------------------------------------------
// Pass 3 (2 light phases, 4 resident tiles, high occupancy):
//  phase B: accY[l][p] = sum_n C[l][n]*S'[p][n]  (manual frags; tiles T0=C,T1=S)
//  reload:  G -> T1 (pre-split copy), X -> T0 (split)
//  phase A: accY += G^T (LDSM.trans) * X (LDSM.trans)
//  final: Y[l][p] = ecl[l]*accY
// ---------------------------------------------------------------------------
__global__ void __launch_bounds__(128, 5) pass3_kernel(
    const float* __restrict__ X, const float* __restrict__ A,
    const float* __restrict__ C, float* __restrict__ Y)
{
    extern __shared__ char smem[];
    __shared__ float s_cs[64], s_ecl[64];

    const int c = blockIdx.x, h = blockIdx.y, b = blockIdx.z;
    const int bhc = (b*NH + h)*NC + c;
    const int tid = threadIdx.x;
    const int tx = tid & 15, ty = tid >> 4;
    const size_t base = ((size_t)((b*4096 + c*64)*NH + h))*64;
    const float* Sg = g_states + (size_t)bhc*4096;
    const int col4 = tx*4;

    if (tid < 64) {
        float v = A[(size_t)(b*4096 + c*64 + tid)*NH + h];
        #pragma unroll
        for (int o = 1; o < 32; o <<= 1) {
            float t = __shfl_up_sync(0xffffffffu, v, o);
            if ((tid & 31) >= o) v += t;
        }
        s_cs[tid] = v;
    }

    // phase-B tiles: C -> T0, S -> T1
    #pragma unroll
    for (int i = 0; i < 8; i++) {
        const int row = i*8 + ty;
        float4 cf = *(const float4*)(C + base + (size_t)row*1024 + col4);
        float4 sf = *(const float4*)(Sg + row*64 + col4);
        split4_store(cf, smem + P3_T0H + row*PB + col4*2,
                         smem + P3_T0L + row*PB + col4*2);
        split4_store(sf, smem + P3_T1H + row*PB + col4*2,
                         smem + P3_T1L + row*PB + col4*2);
    }
    __syncthreads();
    if (tid >= 32 && tid < 64) s_cs[tid] += s_cs[31];
    __syncthreads();
    if (tid < 64) s_ecl[tid] = __expf(s_cs[tid]);

    const int w = tid >> 5, lane = tid & 31;
    const int gq = lane >> 2, t4 = lane & 3;
    const int r0 = 16*w + gq;

    unsigned ah[16], al[16];
    float accY[8][4];
    #pragma unroll
    for (int nt = 0; nt < 8; nt++)
        #pragma unroll
        for (int j = 0; j < 4; j++) accY[nt][j] = 0.f;

    // ---- phase B: A=C[l][n] (manual), Bop=S'[p][n] (manual) ----
    #pragma unroll
    for (int kt = 0; kt < 4; kt++) {
        const int kb = (kt*16 + 2*t4)*2;
        ah[kt*4+0] = *(const unsigned*)(smem + P3_T0H + (r0  )*PB + kb);
        ah[kt*4+1] = *(const unsigned*)(smem + P3_T0H + (r0+8)*PB + kb);
        ah[kt*4+2] = *(const unsigned*)(smem + P3_T0H + (r0  )*PB + kb + 16);
        ah[kt*4+3] = *(const unsigned*)(smem + P3_T0H + (r0+8)*PB + kb + 16);
        al[kt*4+0] = *(const unsigned*)(smem + P3_T0L + (r0  )*PB + kb);
        al[kt*4+1] = *(const unsigned*)(smem + P3_T0L + (r0+8)*PB + kb);
        al[kt*4+2] = *(const unsigned*)(smem + P3_T0L + (r0  )*PB + kb + 16);
        al[kt*4+3] = *(const unsigned*)(smem + P3_T0L + (r0+8)*PB + kb + 16);
    }
    #pragma unroll
    for (int nt = 0; nt < 8; nt++) {
        #pragma unroll
        for (int kt = 0; kt < 4; kt++) {
            const int kb = (kt*16 + 2*t4)*2;
            const char* pr = smem + (nt*8 + gq)*PB + kb;
            unsigned bh0 = *(const unsigned*)(pr + P3_T1H);
            unsigned bh1 = *(const unsigned*)(pr + P3_T1H + 16);
            unsigned bl0 = *(const unsigned*)(pr + P3_T1L);
            unsigned bl1 = *(const unsigned*)(pr + P3_T1L + 16);
            MMA_BF16(accY[nt], ah[kt*4+0], ah[kt*4+1], ah[kt*4+2], ah[kt*4+3], bh0, bh1);
            MMA_BF16(accY[nt], ah[kt*4+0], ah[kt*4+1], ah[kt*4+2], ah[kt*4+3], bl0, bl1);
            MMA_BF16(accY[nt], al[kt*4+0], al[kt*4+1], al[kt*4+2], al[kt*4+3], bh0, bh1);
        }
    }
    __syncthreads();   // C,S tiles dead

    // reload: G (pre-split) -> T1; X (split) -> T0
    {
        const unsigned* gh = g_Gh + bhc*2048;
        const unsigned* gl = g_Gl + bhc*2048;
        #pragma unroll
        for (int i = 0; i < 8; i++) {
            const int row = i*8 + ty;
            float4 xf = *(const float4*)(X + base + (size_t)row*1024 + col4);
            split4_store(xf, smem + P3_T0H + row*PB + col4*2,
                             smem + P3_T0L + row*PB + col4*2);
            *(uint2*)(smem + P3_T1H + row*PB + col4*2) =
                *(const uint2*)(gh + row*32 + (col4>>1));
            *(uint2*)(smem + P3_T1L + row*PB + col4*2) =
                *(const uint2*)(gl + row*32 + (col4>>1));
        }
    }
    __syncthreads();

    // ---- phase A: A=G^T via LDSM.trans (T1 = G[s][l]); Bop=X^T via LDSM.trans ----
    #pragma unroll
    for (int kt = 0; kt < 4; kt++) {
        ldsm4_a_trans(smem + P3_T1H, kt, 16*w, lane,
                      ah[kt*4+0], ah[kt*4+1], ah[kt*4+2], ah[kt*4+3]);
        ldsm4_a_trans(smem + P3_T1L, kt, 16*w, lane,
                      al[kt*4+0], al[kt*4+1], al[kt*4+2], al[kt*4+3]);
    }
    #pragma unroll
    for (int nt = 0; nt < 8; nt++) {
        #pragma unroll
        for (int kh = 0; kh < 2; kh++) {
            unsigned bh0,bh1,bh2,bh3, bl0,bl1,bl2,bl3;
            ldsm4_b_trans(smem + P3_T0H, kh, nt, lane, bh0,bh1,bh2,bh3);
            ldsm4_b_trans(smem + P3_T0L, kh, nt, lane, bl0,bl1,bl2,bl3);
            const int k0 = (kh*2)*4, k1 = (kh*2+1)*4;
            MMA_BF16(accY[nt], ah[k0+0], ah[k0+1], ah[k0+2], ah[k0+3], bh0, bh1);
            MMA_BF16(accY[nt], ah[k0+0], ah[k0+1], ah[k0+2], ah[k0+3], bl0, bl1);
            MMA_BF16(accY[nt], al[k0+0], al[k0+1], al[k0+2], al[k0+3], bh0, bh1);
            MMA_BF16(accY[nt], ah[k1+0], ah[k1+1], ah[k1+2], ah[k1+3], bh2, bh3);
            MMA_BF16(accY[nt], ah[k1+0], ah[k1+1], ah[k1+2], ah[k1+3], bl2, bl3);
            MMA_BF16(accY[nt], al[k1+0], al[k1+1], al[k1+2], al[k1+3], bh2, bh3);
        }
    }

    // final: Y[l][p] = ecl[l] * accY
    {
        const int l0 = r0, l1 = r0 + 8;
        const float e0 = s_ecl[l0], e1 = s_ecl[l1];
        #pragma unroll
        for (int nt = 0; nt < 8; nt++) {
            const int p0 = nt*8 + 2*t4;
            *(float2*)(Y + base + (size_t)l0*1024 + p0) =
                make_float2(e0*accY[nt][0], e0*accY[nt][1]);
            *(float2*)(Y + base + (size_t)l1*1024 + p0) =
                make_float2(e1*accY[nt][2], e1*accY[nt][3]);
        }
    }
}

// ---------------------------------------------------------------------------
extern "C" void kernel_launch(void* const* d_in, const int* in_sizes, int n_in,
                              void* d_out, int out_size)
{
    const float* X = (const float*)d_in[0];
    const float* A = (const float*)d_in[1];
    const float* B = (const float*)d_in[2];
    const float* C = (const float*)d_in[3];
    float* Y = (float*)d_out;

    cudaFuncSetAttribute(gemm13_kernel,
                         cudaFuncAttributeMaxDynamicSharedMemorySize, SMEMG1);
    cudaFuncSetAttribute(pass3_kernel,
                         cudaFuncAttributeMaxDynamicSharedMemorySize, SMEMP3);

    dim3 grid(NC, NH, NB);
    gemm13_kernel<<<grid, 128, SMEMG1>>>(X, A, B, C);
    pass2_kernel<<<dim3(8, NB*NH), 128>>>();
    pass3_kernel<<<grid, 128, SMEMP3>>>(X, A, C, Y);
}

// round 16
// speedup vs baseline: 1.2862x; 1.2862x over previous
#include <cuda_runtime.h>
#include <cuda_bf16.h>

// Problem constants: b=2, s=4096, h=16, p=n=64, BLOCK_LEN=64
#define NB   2
#define NH   16
#define NC   64
#define PB   144   // bf16 tile row pitch in BYTES (72 bf16) -> LDSM conflict-free

// pass3 smem tile offsets (bytes): 6 resident tiles (lifetime reuse)
#define OFF_BH 0
#define OFF_BL 9216
#define OFF_CH 18432
#define OFF_CL 27648
#define OFF_SH 36864
#define OFF_SL 46080
#define SMEM3  55296
#define OFF_GH OFF_SH
#define OFF_GL OFF_SL
#define OFF_XH OFF_BH
#define OFF_XL OFF_BL

// gemm3 smem tile offsets (bytes)
#define G3_XH 0
#define G3_XL 9216
#define G3_BH 18432
#define G3_BL 27648
#define SMEMG3 36864

// Scratch (__device__ globals; allocation-free rule)
__device__ float g_states[NB*NH*NC*4096]; // chunk states [p][n]; scanned in place
__device__ float g_tot[NB*NH*NC];         // per-chunk A totals

#define MMA_BF16(d, a0, a1, a2, a3, b0, b1)                               \
    asm("mma.sync.aligned.m16n8k16.row.col.f32.bf16.bf16.f32 "            \
        "{%0,%1,%2,%3}, {%4,%5,%6,%7}, {%8,%9}, {%0,%1,%2,%3};"           \
        : "+f"(d[0]), "+f"(d[1]), "+f"(d[2]), "+f"(d[3])                  \
        : "r"(a0), "r"(a1), "r"(a2), "r"(a3), "r"(b0), "r"(b1))

// cheap exact 2-term split: hi = mantissa-truncated bf16 (1 PRMT per pair),
// lo = v - hi rounded to bf16 (2 FSUB + 1 cvt per pair). STS.64 stores.
__device__ __forceinline__ unsigned pack_hi2(float a, float b) {
    return __byte_perm(__float_as_uint(a), __float_as_uint(b), 0x7632);
}
__device__ __forceinline__ unsigned pack_lo2(float a, float b) {
    const float la = a - __uint_as_float(__float_as_uint(a) & 0xFFFF0000u);
    const float lb = b - __uint_as_float(__float_as_uint(b) & 0xFFFF0000u);
    unsigned r;
    asm("cvt.rn.bf16x2.f32 %0, %1, %2;" : "=r"(r) : "f"(lb), "f"(la));
    return r;
}
__device__ __forceinline__ void split4_store(float4 v, char* hp, char* lp) {
    *(uint2*)(hp) = make_uint2(pack_hi2(v.x, v.y), pack_hi2(v.z, v.w));
    *(uint2*)(lp) = make_uint2(pack_lo2(v.x, v.y), pack_lo2(v.z, v.w));
}

// A-fragment (m16k16) from k-major storage T[k][m] via ldmatrix.trans.
__device__ __forceinline__ void ldsm4_a_trans(
    const char* tile, int kt, int mbase, int lane,
    unsigned& a0, unsigned& a1, unsigned& a2, unsigned& a3)
{
    const int row  = kt*16 + ((lane>>4)<<3) + (lane&7);
    const int colb = (mbase + ((lane>>3)&1)*8)*2;
    unsigned addr = (unsigned)__cvta_generic_to_shared(tile + row*PB + colb);
    asm volatile("ldmatrix.sync.aligned.m8n8.x4.trans.shared.b16 {%0,%1,%2,%3}, [%4];"
                 : "=r"(a0),"=r"(a1),"=r"(a2),"=r"(a3) : "r"(addr));
}
// B-fragments for two consecutive k16 blocks from k-major storage T[k][n].
__device__ __forceinline__ void ldsm4_b_trans(
    const char* tile, int khalf, int nt, int lane,
    unsigned& b0, unsigned& b1, unsigned& b2, unsigned& b3)
{
    unsigned addr = (unsigned)__cvta_generic_to_shared(
        tile + (khalf*32 + lane)*PB + nt*16);
    asm volatile("ldmatrix.sync.aligned.m8n8.x4.trans.shared.b16 {%0,%1,%2,%3}, [%4];"
                 : "=r"(b0),"=r"(b1),"=r"(b2),"=r"(b3) : "r"(addr));
}

// ---------------------------------------------------------------------------
// Kernel 1 (tensor + LDSM): S'[p][n] = sum_l (w[l]*X[l][p]) * B[l][n].
// LDG-first prep: X parked in regs, B split-stored, overlapping the cumsum.
// ---------------------------------------------------------------------------
__global__ void __launch_bounds__(128, 4) gemm3_kernel(
    const float* __restrict__ X, const float* __restrict__ A,
    const float* __restrict__ B)
{
    extern __shared__ char smem[];
    __shared__ float s_cs[64], s_w[64];

    const int c = blockIdx.x, h = blockIdx.y, b = blockIdx.z;
    const int bhc = (b*NH + h)*NC + c;
    const int tid = threadIdx.x;
    const int tx = tid & 15, ty = tid >> 4;
    const size_t base = ((size_t)((b*4096 + c*64)*NH + h))*64;
    const int col4 = tx*4;

    // warp-level scan starts (no sync yet)
    float csv = 0.f;
    if (tid < 64) {
        float v = A[(size_t)(b*4096 + c*64 + tid)*NH + h];
        #pragma unroll
        for (int o = 1; o < 32; o <<= 1) {
            float t = __shfl_up_sync(0xffffffffu, v, o);
            if ((tid & 31) >= o) v += t;
        }
        csv = v;
        s_cs[tid] = v;
    }

    // LDG-first: X into regs, B split-stored immediately (overlaps scan)
    float4 xreg[8];
    #pragma unroll
    for (int i = 0; i < 8; i++) {
        const int row = i*8 + ty;
        const size_t g = base + (size_t)row*1024 + col4;
        xreg[i] = *(const float4*)(X + g);
        float4 bf = *(const float4*)(B + g);
        split4_store(bf, smem + G3_BH + row*PB + col4*2,
                         smem + G3_BL + row*PB + col4*2);
    }
    __syncthreads();
    if (tid >= 32 && tid < 64) s_cs[tid] += s_cs[31];
    __syncthreads();
    if (tid < 64) {
        s_w[tid] = __expf(s_cs[63] - s_cs[tid]);
        if (tid == 63) g_tot[bhc] = s_cs[63];
    }
    (void)csv;
    __syncthreads();

    // scale X by w, split-store
    #pragma unroll
    for (int i = 0; i < 8; i++) {
        const int row = i*8 + ty;
        float4 xf = xreg[i];
        const float w = s_w[row];
        xf.x *= w; xf.y *= w; xf.z *= w; xf.w *= w;
        split4_store(xf, smem + G3_XH + row*PB + col4*2,
                         smem + G3_XL + row*PB + col4*2);
    }
    __syncthreads();

    const int w = tid >> 5, lane = tid & 31;
    const int gq = lane >> 2, t4 = lane & 3;
    const int r0 = 16*w + gq;                        // p-row base

    unsigned ah[16], al[16];
    #pragma unroll
    for (int kt = 0; kt < 4; kt++) {
        ldsm4_a_trans(smem + G3_XH, kt, 16*w, lane,
                      ah[kt*4+0], ah[kt*4+1], ah[kt*4+2], ah[kt*4+3]);
        ldsm4_a_trans(smem + G3_XL, kt, 16*w, lane,
                      al[kt*4+0], al[kt*4+1], al[kt*4+2], al[kt*4+3]);
    }

    float acc[8][4];
    #pragma unroll
    for (int nt = 0; nt < 8; nt++)
        #pragma unroll
        for (int j = 0; j < 4; j++) acc[nt][j] = 0.f;

    #pragma unroll
    for (int nt = 0; nt < 8; nt++) {
        #pragma unroll
        for (int kh = 0; kh < 2; kh++) {
            unsigned bh0,bh1,bh2,bh3, bl0,bl1,bl2,bl3;
            ldsm4_b_trans(smem + G3_BH, kh, nt, lane, bh0,bh1,bh2,bh3);
            ldsm4_b_trans(smem + G3_BL, kh, nt, lane, bl0,bl1,bl2,bl3);
            const int k0 = (kh*2)*4, k1 = (kh*2+1)*4;
            MMA_BF16(acc[nt], ah[k0+0], ah[k0+1], ah[k0+2], ah[k0+3], bh0, bh1);
            MMA_BF16(acc[nt], ah[k0+0], ah[k0+1], ah[k0+2], ah[k0+3], bl0, bl1);
            MMA_BF16(acc[nt], al[k0+0], al[k0+1], al[k0+2], al[k0+3], bh0, bh1);
            MMA_BF16(acc[nt], ah[k1+0], ah[k1+1], ah[k1+2], ah[k1+3], bh2, bh3);
            MMA_BF16(acc[nt], ah[k1+0], ah[k1+1], ah[k1+2], ah[k1+3], bl2, bl3);
            MMA_BF16(acc[nt], al[k1+0], al[k1+1], al[k1+2], al[k1+3], bh2, bh3);
        }
    }

    float* st = g_states + (size_t)bhc*4096;
    const int p0 = r0, p1 = r0 + 8;
    #pragma unroll
    for (int nt = 0; nt < 8; nt++) {
        const int n0 = nt*8 + 2*t4;
        *(float2*)(st + p0*64 + n0) = make_float2(acc[nt][0], acc[nt][1]);
        *(float2*)(st + p1*64 + n0) = make_float2(acc[nt][2], acc[nt][3]);
    }
}

// ---------------------------------------------------------------------------
// Pass 2: inter-chunk scan, in place (fp32).
// ---------------------------------------------------------------------------
__global__ void __launch_bounds__(128) pass2_kernel()
{
    __shared__ float se[NC];
    const int slice = blockIdx.x, bh = blockIdx.y;
    const int tid = threadIdx.x;

    if (tid < NC) se[tid] = __expf(g_tot[bh*NC + tid]);
    __syncthreads();

    float* p = g_states + (size_t)bh*NC*4096 + slice*512 + tid*4;
    float4 v[8];
    #pragma unroll
    for (int j = 0; j < 8; j++) v[j] = *(float4*)(p + (size_t)j*4096);

    float4 S = make_float4(0.f, 0.f, 0.f, 0.f);
    #pragma unroll 8
    for (int c = 0; c < NC; c++) {
        float4 cur = v[c & 7];
        *(float4*)(p + (size_t)c*4096) = S;
        const float e = se[c];
        S.x = e * (S.x + cur.x);
        S.y = e * (S.y + cur.y);
        S.z = e * (S.z + cur.z);
        S.w = e * (S.w + cur.w);
        if (c + 8 < NC) v[c & 7] = *(float4*)(p + (size_t)(c+8)*4096);
    }
}

// ---------------------------------------------------------------------------
// Pass 3 (tensor cores, 6 resident tiles, 4 CTAs/SM) — R14 structure:
//  prep:    B,C,S split-stored (straight)
//  GEMM1:   accG[s][l] = sum_n B[s][n]*C[l][n]        (manual frags)
//  phase B: accY[l][p] = sum_n C[l][n]*S'[p][n]       (manual frags)
//  sync; epi: G[s][l] (mask,em) -> over dead S tiles; X loaded+split over dead B
//  sync; phase A: accY += G^T (LDSM.trans) * X (LDSM.trans)
//  final: Y[l][p] = ecl[l]*accY
// ---------------------------------------------------------------------------
__global__ void __launch_bounds__(128, 4) pass3_kernel(
    const float* __restrict__ X, const float* __restrict__ A,
    const float* __restrict__ B, const float* __restrict__ C,
    float* __restrict__ Y)
{
    extern __shared__ char smem[];
    __shared__ float s_cs[64], s_ecl[64], s_em[64];

    const int c = blockIdx.x, h = blockIdx.y, b = blockIdx.z;
    const int bhc = (b*NH + h)*NC + c;
    const int tid = threadIdx.x;
    const int tx = tid & 15, ty = tid >> 4;
    const size_t base = ((size_t)((b*4096 + c*64)*NH + h))*64;
    const float* Sg = g_states + (size_t)bhc*4096;
    const int col4 = tx*4;

    if (tid < 64) {
        const float av = A[(size_t)(b*4096 + c*64 + tid)*NH + h];
        float v = av;
        #pragma unroll
        for (int o = 1; o < 32; o <<= 1) {
            float t = __shfl_up_sync(0xffffffffu, v, o);
            if ((tid & 31) >= o) v += t;
        }
        s_cs[tid] = v;
        s_em[tid] = av;
    }

    // prep: B, C, S split-stored straight (X deferred)
    #pragma unroll
    for (int i = 0; i < 8; i++) {
        const int row = i*8 + ty;
        const size_t g = base + (size_t)row*1024 + col4;
        float4 bf = *(const float4*)(B + g);
        float4 cf = *(const float4*)(C + g);
        float4 sf = *(const float4*)(Sg + row*64 + col4);
        split4_store(bf, smem + OFF_BH + row*PB + col4*2,
                         smem + OFF_BL + row*PB + col4*2);
        split4_store(cf, smem + OFF_CH + row*PB + col4*2,
                         smem + OFF_CL + row*PB + col4*2);
        split4_store(sf, smem + OFF_SH + row*PB + col4*2,
                         smem + OFF_SL + row*PB + col4*2);
    }
    __syncthreads();
    if (tid >= 32 && tid < 64) s_cs[tid] += s_cs[31];
    __syncthreads();
    if (tid < 64) {
        const float csl = s_cs[tid];
        s_ecl[tid] = __expf(csl);
        s_em[tid]  = __expf(s_em[tid] - csl);
    }
    __syncthreads();

    const int w = tid >> 5, lane = tid & 31;
    const int gq = lane >> 2, t4 = lane & 3;
    const int r0 = 16*w + gq;

    unsigned ah[16], al[16];
    float accG[8][4], accY[8][4];
    #pragma unroll
    for (int nt = 0; nt < 8; nt++)
        #pragma unroll
        for (int j = 0; j < 4; j++) { accG[nt][j] = 0.f; accY[nt][j] = 0.f; }

    // ---- GEMM1: A=B[s][n], Bop=C[l][n] -> accG[s][l] ----
    #pragma unroll
    for (int kt = 0; kt < 4; kt++) {
        const int kb = (kt*16 + 2*t4)*2;
        ah[kt*4+0] = *(const unsigned*)(smem + OFF_BH + (r0  )*PB + kb);
        ah[kt*4+1] = *(const unsigned*)(smem + OFF_BH + (r0+8)*PB + kb);
        ah[kt*4+2] = *(const unsigned*)(smem + OFF_BH + (r0  )*PB + kb + 16);
        ah[kt*4+3] = *(const unsigned*)(smem + OFF_BH + (r0+8)*PB + kb + 16);
        al[kt*4+0] = *(const unsigned*)(smem + OFF_BL + (r0  )*PB + kb);
        al[kt*4+1] = *(const unsigned*)(smem + OFF_BL + (r0+8)*PB + kb);
        al[kt*4+2] = *(const unsigned*)(smem + OFF_BL + (r0  )*PB + kb + 16);
        al[kt*4+3] = *(const unsigned*)(smem + OFF_BL + (r0+8)*PB + kb + 16);
    }
    #pragma unroll
    for (int nt = 0; nt < 8; nt++) {
        #pragma unroll
        for (int kt = 0; kt < 4; kt++) {
            const int kb = (kt*16 + 2*t4)*2;
            const char* pr = smem + (nt*8 + gq)*PB + kb;
            unsigned bh0 = *(const unsigned*)(pr + OFF_CH);
            unsigned bh1 = *(const unsigned*)(pr + OFF_CH + 16);
            unsigned bl0 = *(const unsigned*)(pr + OFF_CL);
            unsigned bl1 = *(const unsigned*)(pr + OFF_CL + 16);
            MMA_BF16(accG[nt], ah[kt*4+0], ah[kt*4+1], ah[kt*4+2], ah[kt*4+3], bh0, bh1);
            MMA_BF16(accG[nt], ah[kt*4+0], ah[kt*4+1], ah[kt*4+2], ah[kt*4+3], bl0, bl1);
            MMA_BF16(accG[nt], al[kt*4+0], al[kt*4+1], al[kt*4+2], al[kt*4+3], bh0, bh1);
        }
    }

    // ---- phase B: A=C[l][n], Bop=S'[p][n] -> accY[l][p] ----
    #pragma unroll
    for (int kt = 0; kt < 4; kt++) {
        const int kb = (kt*16 + 2*t4)*2;
        ah[kt*4+0] = *(const unsigned*)(smem + OFF_CH + (r0  )*PB + kb);
        ah[kt*4+1] = *(const unsigned*)(smem + OFF_CH + (r0+8)*PB + kb);
        ah[kt*4+2] = *(const unsigned*)(smem + OFF_CH + (r0  )*PB + kb + 16);
        ah[kt*4+3] = *(const unsigned*)(smem + OFF_CH + (r0+8)*PB + kb + 16);
        al[kt*4+0] = *(const unsigned*)(smem + OFF_CL + (r0  )*PB + kb);
        al[kt*4+1] = *(const unsigned*)(smem + OFF_CL + (r0+8)*PB + kb);
        al[kt*4+2] = *(const unsigned*)(smem + OFF_CL + (r0  )*PB + kb + 16);
        al[kt*4+3] = *(const unsigned*)(smem + OFF_CL + (r0+8)*PB + kb + 16);
    }
    #pragma unroll
    for (int nt = 0; nt < 8; nt++) {
        #pragma unroll
        for (int kt = 0; kt < 4; kt++) {
            const int kb = (kt*16 + 2*t4)*2;
            const char* pr = smem + (nt*8 + gq)*PB + kb;
            unsigned bh0 = *(const unsigned*)(pr + OFF_SH);
            unsigned bh1 = *(const unsigned*)(pr + OFF_SH + 16);
            unsigned bl0 = *(const unsigned*)(pr + OFF_SL);
            unsigned bl1 = *(const unsigned*)(pr + OFF_SL + 16);
            MMA_BF16(accY[nt], ah[kt*4+0], ah[kt*4+1], ah[kt*4+2], ah[kt*4+3], bh0, bh1);
            MMA_BF16(accY[nt], ah[kt*4+0], ah[kt*4+1], ah[kt*4+2], ah[kt*4+3], bl0, bl1);
            MMA_BF16(accY[nt], al[kt*4+0], al[kt*4+1], al[kt*4+2], al[kt*4+3], bh0, bh1);
        }
    }
    __syncthreads();   // B and S tiles now dead everywhere

    // epilogue: G[s][l] (mask, em) -> over S tiles
    {
        const int s0 = r0, s1 = r0 + 8;
        const float em0 = s_em[s0], em1 = s_em[s1];
        #pragma unroll
        for (int nt = 0; nt < 8; nt++) {
            const int l0 = nt*8 + 2*t4;
            float v00 = (l0   >= s0) ? accG[nt][0]*em0 : 0.f;
            float v01 = (l0+1 >= s0) ? accG[nt][1]*em0 : 0.f;
            float v10 = (l0   >= s1) ? accG[nt][2]*em1 : 0.f;
            float v11 = (l0+1 >= s1) ? accG[nt][3]*em1 : 0.f;
            *(unsigned*)(smem + OFF_GH + s0*PB + l0*2) = pack_hi2(v00, v01);
            *(unsigned*)(smem + OFF_GL + s0*PB + l0*2) = pack_lo2(v00, v01);
            *(unsigned*)(smem + OFF_GH + s1*PB + l0*2) = pack_hi2(v10, v11);
            *(unsigned*)(smem + OFF_GL + s1*PB + l0*2) = pack_lo2(v10, v11);
        }
    }
    // deferred X load+split -> over B tiles
    #pragma unroll
    for (int i = 0; i < 8; i++) {
        const int row = i*8 + ty;
        float4 xf = *(const float4*)(X + base + (size_t)row*1024 + col4);
        split4_store(xf, smem + OFF_XH + row*PB + col4*2,
                         smem + OFF_XL + row*PB + col4*2);
    }
    __syncthreads();

    // ---- phase A: accY += G^T * X (both via LDSM.trans) ----
    #pragma unroll
    for (int kt = 0; kt < 4; kt++) {
        ldsm4_a_trans(smem + OFF_GH, kt, 16*w, lane,
                      ah[kt*4+0], ah[kt*4+1], ah[kt*4+2], ah[kt*4+3]);
        ldsm4_a_trans(smem + OFF_GL, kt, 16*w, lane,
                      al[kt*4+0], al[kt*4+1], al[kt*4+2], al[kt*4+3]);
    }
    #pragma unroll
    for (int nt = 0; nt < 8; nt++) {
        #pragma unroll
        for (int kh = 0; kh < 2; kh++) {
            unsigned bh0,bh1,bh2,bh3, bl0,bl1,bl2,bl3;
            ldsm4_b_trans(smem + OFF_XH, kh, nt, lane, bh0,bh1,bh2,bh3);
            ldsm4_b_trans(smem + OFF_XL, kh, nt, lane, bl0,bl1,bl2,bl3);
            const int k0 = (kh*2)*4, k1 = (kh*2+1)*4;
            MMA_BF16(accY[nt], ah[k0+0], ah[k0+1], ah[k0+2], ah[k0+3], bh0, bh1);
            MMA_BF16(accY[nt], ah[k0+0], ah[k0+1], ah[k0+2], ah[k0+3], bl0, bl1);
            MMA_BF16(accY[nt], al[k0+0], al[k0+1], al[k0+2], al[k0+3], bh0, bh1);
            MMA_BF16(accY[nt], ah[k1+0], ah[k1+1], ah[k1+2], ah[k1+3], bh2, bh3);
            MMA_BF16(accY[nt], ah[k1+0], ah[k1+1], ah[k1+2], ah[k1+3], bl2, bl3);
            MMA_BF16(accY[nt], al[k1+0], al[k1+1], al[k1+2], al[k1+3], bh2, bh3);
        }
    }

    // final: Y[l][p] = ecl[l] * accY
    {
        const int l0 = r0, l1 = r0 + 8;
        const float e0 = s_ecl[l0], e1 = s_ecl[l1];
        #pragma unroll
        for (int nt = 0; nt < 8; nt++) {
            const int p0 = nt*8 + 2*t4;
            *(float2*)(Y + base + (size_t)l0*1024 + p0) =
                make_float2(e0*accY[nt][0], e0*accY[nt][1]);
            *(float2*)(Y + base + (size_t)l1*1024 + p0) =
                make_float2(e1*accY[nt][2], e1*accY[nt][3]);
        }
    }
}

// ---------------------------------------------------------------------------
extern "C" void kernel_launch(void* const* d_in, const int* in_sizes, int n_in,
                              void* d_out, int out_size)
{
    const float* X = (const float*)d_in[0];
    const float* A = (const float*)d_in[1];
    const float* B = (const float*)d_in[2];
    const float* C = (const float*)d_in[3];
    float* Y = (float*)d_out;

    cudaFuncSetAttribute(gemm3_kernel,
                         cudaFuncAttributeMaxDynamicSharedMemorySize, SMEMG3);
    cudaFuncSetAttribute(pass3_kernel,
                         cudaFuncAttributeMaxDynamicSharedMemorySize, SMEM3);

    dim3 grid(NC, NH, NB);
    gemm3_kernel<<<grid, 128, SMEMG3>>>(X, A, B);
    pass2_kernel<<<dim3(8, NB*NH), 128>>>();
    pass3_kernel<<<grid, 128, SMEM3>>>(X, A, B, C, Y);
}

// round 17
// speedup vs baseline: 1.3094x; 1.0180x over previous
#include <cuda_runtime.h>
#include <cuda_bf16.h>

// Problem constants: b=2, s=4096, h=16, p=n=64, BLOCK_LEN=64
#define NB   2
#define NH   16
#define NC   64
#define PB   144   // bf16 tile row pitch in BYTES (72 bf16) -> LDSM conflict-free

// pass3 smem tile offsets (bytes): 6 resident tiles (lifetime reuse)
//   T(B): B then G ; T(C): C ; T(S): S then X
#define OFF_BH 0
#define OFF_BL 9216
#define OFF_CH 18432
#define OFF_CL 27648
#define OFF_SH 36864
#define OFF_SL 46080
#define SMEM3  55296
#define OFF_GH OFF_BH
#define OFF_GL OFF_BL
#define OFF_XH OFF_SH
#define OFF_XL OFF_SL

// gemm3 smem tile offsets (bytes)
#define G3_XH 0
#define G3_XL 9216
#define G3_BH 18432
#define G3_BL 27648
#define SMEMG3 36864

// Scratch (__device__ globals; allocation-free rule)
__device__ float g_states[NB*NH*NC*4096]; // chunk states [p][n]; scanned in place
__device__ float g_tot[NB*NH*NC];         // per-chunk A totals

#define MMA_BF16(d, a0, a1, a2, a3, b0, b1)                               \
    asm("mma.sync.aligned.m16n8k16.row.col.f32.bf16.bf16.f32 "            \
        "{%0,%1,%2,%3}, {%4,%5,%6,%7}, {%8,%9}, {%0,%1,%2,%3};"           \
        : "+f"(d[0]), "+f"(d[1]), "+f"(d[2]), "+f"(d[3])                  \
        : "r"(a0), "r"(a1), "r"(a2), "r"(a3), "r"(b0), "r"(b1))

// cheap exact 2-term split: hi = mantissa-truncated bf16 (1 PRMT per pair),
// lo = v - hi rounded to bf16 (2 FSUB + 1 cvt per pair). STS.64 stores.
__device__ __forceinline__ unsigned pack_hi2(float a, float b) {
    return __byte_perm(__float_as_uint(a), __float_as_uint(b), 0x7632);
}
__device__ __forceinline__ unsigned pack_lo2(float a, float b) {
    const float la = a - __uint_as_float(__float_as_uint(a) & 0xFFFF0000u);
    const float lb = b - __uint_as_float(__float_as_uint(b) & 0xFFFF0000u);
    unsigned r;
    asm("cvt.rn.bf16x2.f32 %0, %1, %2;" : "=r"(r) : "f"(lb), "f"(la));
    return r;
}
__device__ __forceinline__ void split4_store(float4 v, char* hp, char* lp) {
    *(uint2*)(hp) = make_uint2(pack_hi2(v.x, v.y), pack_hi2(v.z, v.w));
    *(uint2*)(lp) = make_uint2(pack_lo2(v.x, v.y), pack_lo2(v.z, v.w));
}

// A-fragment (m16k16) from k-major storage T[k][m] via ldmatrix.trans.
__device__ __forceinline__ void ldsm4_a_trans(
    const char* tile, int kt, int mbase, int lane,
    unsigned& a0, unsigned& a1, unsigned& a2, unsigned& a3)
{
    const int row  = kt*16 + ((lane>>4)<<3) + (lane&7);
    const int colb = (mbase + ((lane>>3)&1)*8)*2;
    unsigned addr = (unsigned)__cvta_generic_to_shared(tile + row*PB + colb);
    asm volatile("ldmatrix.sync.aligned.m8n8.x4.trans.shared.b16 {%0,%1,%2,%3}, [%4];"
                 : "=r"(a0),"=r"(a1),"=r"(a2),"=r"(a3) : "r"(addr));
}
// B-fragments for two consecutive k16 blocks from k-major storage T[k][n].
__device__ __forceinline__ void ldsm4_b_trans(
    const char* tile, int khalf, int nt, int lane,
    unsigned& b0, unsigned& b1, unsigned& b2, unsigned& b3)
{
    unsigned addr = (unsigned)__cvta_generic_to_shared(
        tile + (khalf*32 + lane)*PB + nt*16);
    asm volatile("ldmatrix.sync.aligned.m8n8.x4.trans.shared.b16 {%0,%1,%2,%3}, [%4];"
                 : "=r"(b0),"=r"(b1),"=r"(b2),"=r"(b3) : "r"(addr));
}

// ---------------------------------------------------------------------------
// Kernel 1 (tensor + LDSM): S'[p][n] = sum_l (w[l]*X[l][p]) * B[l][n].
// LDG-first prep: X parked in regs, B split-stored, overlapping the cumsum.
// ---------------------------------------------------------------------------
__global__ void __launch_bounds__(128, 4) gemm3_kernel(
    const float* __restrict__ X, const float* __restrict__ A,
    const float* __restrict__ B)
{
    extern __shared__ char smem[];
    __shared__ float s_cs[64], s_w[64];

    const int c = blockIdx.x, h = blockIdx.y, b = blockIdx.z;
    const int bhc = (b*NH + h)*NC + c;
    const int tid = threadIdx.x;
    const int tx = tid & 15, ty = tid >> 4;
    const size_t base = ((size_t)((b*4096 + c*64)*NH + h))*64;
    const int col4 = tx*4;

    if (tid < 64) {
        float v = A[(size_t)(b*4096 + c*64 + tid)*NH + h];
        #pragma unroll
        for (int o = 1; o < 32; o <<= 1) {
            float t = __shfl_up_sync(0xffffffffu, v, o);
            if ((tid & 31) >= o) v += t;
        }
        s_cs[tid] = v;
    }

    // LDG-first: X into regs, B split-stored immediately (overlaps scan)
    float4 xreg[8];
    #pragma unroll
    for (int i = 0; i < 8; i++) {
        const int row = i*8 + ty;
        const size_t g = base + (size_t)row*1024 + col4;
        xreg[i] = *(const float4*)(X + g);
        float4 bf = *(const float4*)(B + g);
        split4_store(bf, smem + G3_BH + row*PB + col4*2,
                         smem + G3_BL + row*PB + col4*2);
    }
    __syncthreads();
    if (tid >= 32 && tid < 64) s_cs[tid] += s_cs[31];
    __syncthreads();
    if (tid < 64) {
        s_w[tid] = __expf(s_cs[63] - s_cs[tid]);
        if (tid == 63) g_tot[bhc] = s_cs[63];
    }
    __syncthreads();

    // scale X by w, split-store
    #pragma unroll
    for (int i = 0; i < 8; i++) {
        const int row = i*8 + ty;
        float4 xf = xreg[i];
        const float w = s_w[row];
        xf.x *= w; xf.y *= w; xf.z *= w; xf.w *= w;
        split4_store(xf, smem + G3_XH + row*PB + col4*2,
                         smem + G3_XL + row*PB + col4*2);
    }
    __syncthreads();

    const int w = tid >> 5, lane = tid & 31;
    const int gq = lane >> 2, t4 = lane & 3;
    const int r0 = 16*w + gq;                        // p-row base

    unsigned ah[16], al[16];
    #pragma unroll
    for (int kt = 0; kt < 4; kt++) {
        ldsm4_a_trans(smem + G3_XH, kt, 16*w, lane,
                      ah[kt*4+0], ah[kt*4+1], ah[kt*4+2], ah[kt*4+3]);
        ldsm4_a_trans(smem + G3_XL, kt, 16*w, lane,
                      al[kt*4+0], al[kt*4+1], al[kt*4+2], al[kt*4+3]);
    }

    float acc[8][4];
    #pragma unroll
    for (int nt = 0; nt < 8; nt++)
        #pragma unroll
        for (int j = 0; j < 4; j++) acc[nt][j] = 0.f;

    #pragma unroll
    for (int nt = 0; nt < 8; nt++) {
        #pragma unroll
        for (int kh = 0; kh < 2; kh++) {
            unsigned bh0,bh1,bh2,bh3, bl0,bl1,bl2,bl3;
            ldsm4_b_trans(smem + G3_BH, kh, nt, lane, bh0,bh1,bh2,bh3);
            ldsm4_b_trans(smem + G3_BL, kh, nt, lane, bl0,bl1,bl2,bl3);
            const int k0 = (kh*2)*4, k1 = (kh*2+1)*4;
            MMA_BF16(acc[nt], ah[k0+0], ah[k0+1], ah[k0+2], ah[k0+3], bh0, bh1);
            MMA_BF16(acc[nt], ah[k0+0], ah[k0+1], ah[k0+2], ah[k0+3], bl0, bl1);
            MMA_BF16(acc[nt], al[k0+0], al[k0+1], al[k0+2], al[k0+3], bh0, bh1);
            MMA_BF16(acc[nt], ah[k1+0], ah[k1+1], ah[k1+2], ah[k1+3], bh2, bh3);
            MMA_BF16(acc[nt], ah[k1+0], ah[k1+1], ah[k1+2], ah[k1+3], bl2, bl3);
            MMA_BF16(acc[nt], al[k1+0], al[k1+1], al[k1+2], al[k1+3], bh2, bh3);
        }
    }

    float* st = g_states + (size_t)bhc*4096;
    const int p0 = r0, p1 = r0 + 8;
    #pragma unroll
    for (int nt = 0; nt < 8; nt++) {
        const int n0 = nt*8 + 2*t4;
        *(float2*)(st + p0*64 + n0) = make_float2(acc[nt][0], acc[nt][1]);
        *(float2*)(st + p1*64 + n0) = make_float2(acc[nt][2], acc[nt][3]);
    }
}

// ---------------------------------------------------------------------------
// Pass 2: inter-chunk scan, in place (fp32).
// ---------------------------------------------------------------------------
__global__ void __launch_bounds__(128) pass2_kernel()
{
    __shared__ float se[NC];
    const int slice = blockIdx.x, bh = blockIdx.y;
    const int tid = threadIdx.x;

    if (tid < NC) se[tid] = __expf(g_tot[bh*NC + tid]);
    __syncthreads();

    float* p = g_states + (size_t)bh*NC*4096 + slice*512 + tid*4;
    float4 v[8];
    #pragma unroll
    for (int j = 0; j < 8; j++) v[j] = *(float4*)(p + (size_t)j*4096);

    float4 S = make_float4(0.f, 0.f, 0.f, 0.f);
    #pragma unroll 8
    for (int c = 0; c < NC; c++) {
        float4 cur = v[c & 7];
        *(float4*)(p + (size_t)c*4096) = S;
        const float e = se[c];
        S.x = e * (S.x + cur.x);
        S.y = e * (S.y + cur.y);
        S.z = e * (S.z + cur.z);
        S.w = e * (S.w + cur.w);
        if (c + 8 < NC) v[c & 7] = *(float4*)(p + (size_t)(c+8)*4096);
    }
}

// ---------------------------------------------------------------------------
// Pass 3 (tensor cores, 6 resident tiles, X latency hidden under phase B):
//  prep:   B,C,S split-stored (straight)
//  GEMM1:  accG[s][l] = sum_n B[s][n]*C[l][n]
//  sync;   epi: G[s][l] -> over dead B tiles (accG dies); X LDG -> regs
//  phaseB: accY[l][p] = sum_n C[l][n]*S'[p][n]   (hides X latency)
//  sync;   X split-store -> over dead S tiles (from regs, no latency)
//  sync;   phase A: accY += G^T (LDSM.trans) * X (LDSM.trans)
//  final:  Y[l][p] = ecl[l]*accY
// ---------------------------------------------------------------------------
__global__ void __launch_bounds__(128, 4) pass3_kernel(
    const float* __restrict__ X, const float* __restrict__ A,
    const float* __restrict__ B, const float* __restrict__ C,
    float* __restrict__ Y)
{
    extern __shared__ char smem[];
    __shared__ float s_cs[64], s_ecl[64], s_em[64];

    const int c = blockIdx.x, h = blockIdx.y, b = blockIdx.z;
    const int bhc = (b*NH + h)*NC + c;
    const int tid = threadIdx.x;
    const int tx = tid & 15, ty = tid >> 4;
    const size_t base = ((size_t)((b*4096 + c*64)*NH + h))*64;
    const float* Sg = g_states + (size_t)bhc*4096;
    const int col4 = tx*4;

    if (tid < 64) {
        const float av = A[(size_t)(b*4096 + c*64 + tid)*NH + h];
        float v = av;
        #pragma unroll
        for (int o = 1; o < 32; o <<= 1) {
            float t = __shfl_up_sync(0xffffffffu, v, o);
            if ((tid & 31) >= o) v += t;
        }
        s_cs[tid] = v;
        s_em[tid] = av;
    }

    // prep: B, C, S split-stored straight (X deferred)
    #pragma unroll
    for (int i = 0; i < 8; i++) {
        const int row = i*8 + ty;
        const size_t g = base + (size_t)row*1024 + col4;
        float4 bf = *(const float4*)(B + g);
        float4 cf = *(const float4*)(C + g);
        float4 sf = *(const float4*)(Sg + row*64 + col4);
        split4_store(bf, smem + OFF_BH + row*PB + col4*2,
                         smem + OFF_BL + row*PB + col4*2);
        split4_store(cf, smem + OFF_CH + row*PB + col4*2,
                         smem + OFF_CL + row*PB + col4*2);
        split4_store(sf, smem + OFF_SH + row*PB + col4*2,
                         smem + OFF_SL + row*PB + col4*2);
    }
    __syncthreads();
    if (tid >= 32 && tid < 64) s_cs[tid] += s_cs[31];
    __syncthreads();
    if (tid < 64) {
        const float csl = s_cs[tid];
        s_ecl[tid] = __expf(csl);
        s_em[tid]  = __expf(s_em[tid] - csl);
    }
    __syncthreads();

    const int w = tid >> 5, lane = tid & 31;
    const int gq = lane >> 2, t4 = lane & 3;
    const int r0 = 16*w + gq;

    unsigned ah[16], al[16];
    float accY[8][4];
    float4 xreg[8];

    // ---- GEMM1: A=B[s][n], Bop=C[l][n] -> accG[s][l] (scoped) ----
    {
        float accG[8][4];
        #pragma unroll
        for (int nt = 0; nt < 8; nt++)
            #pragma unroll
            for (int j = 0; j < 4; j++) accG[nt][j] = 0.f;

        #pragma unroll
        for (int kt = 0; kt < 4; kt++) {
            const int kb = (kt*16 + 2*t4)*2;
            ah[kt*4+0] = *(const unsigned*)(smem + OFF_BH + (r0  )*PB + kb);
            ah[kt*4+1] = *(const unsigned*)(smem + OFF_BH + (r0+8)*PB + kb);
            ah[kt*4+2] = *(const unsigned*)(smem + OFF_BH + (r0  )*PB + kb + 16);
            ah[kt*4+3] = *(const unsigned*)(smem + OFF_BH + (r0+8)*PB + kb + 16);
            al[kt*4+0] = *(const unsigned*)(smem + OFF_BL + (r0  )*PB + kb);
            al[kt*4+1] = *(const unsigned*)(smem + OFF_BL + (r0+8)*PB + kb);
            al[kt*4+2] = *(const unsigned*)(smem + OFF_BL + (r0  )*PB + kb + 16);
            al[kt*4+3] = *(const unsigned*)(smem + OFF_BL + (r0+8)*PB + kb + 16);
        }
        #pragma unroll
        for (int nt = 0; nt < 8; nt++) {
            #pragma unroll
            for (int kt = 0; kt < 4; kt++) {
                const int kb = (kt*16 + 2*t4)*2;
                const char* pr = smem + (nt*8 + gq)*PB + kb;
                unsigned bh0 = *(const unsigned*)(pr + OFF_CH);
                unsigned bh1 = *(const unsigned*)(pr + OFF_CH + 16);
                unsigned bl0 = *(const unsigned*)(pr + OFF_CL);
                unsigned bl1 = *(const unsigned*)(pr + OFF_CL + 16);
                MMA_BF16(accG[nt], ah[kt*4+0], ah[kt*4+1], ah[kt*4+2], ah[kt*4+3], bh0, bh1);
                MMA_BF16(accG[nt], ah[kt*4+0], ah[kt*4+1], ah[kt*4+2], ah[kt*4+3], bl0, bl1);
                MMA_BF16(accG[nt], al[kt*4+0], al[kt*4+1], al[kt*4+2], al[kt*4+3], bh0, bh1);
            }
        }
        __syncthreads();   // B tiles dead everywhere -> reusable for G

        // epilogue: G[s][l] (mask, em) -> over B tiles; accG dies here
        const int s0 = r0, s1 = r0 + 8;
        const float em0 = s_em[s0], em1 = s_em[s1];
        #pragma unroll
        for (int nt = 0; nt < 8; nt++) {
            const int l0 = nt*8 + 2*t4;
            float v00 = (l0   >= s0) ? accG[nt][0]*em0 : 0.f;
            float v01 = (l0+1 >= s0) ? accG[nt][1]*em0 : 0.f;
            float v10 = (l0   >= s1) ? accG[nt][2]*em1 : 0.f;
            float v11 = (l0+1 >= s1) ? accG[nt][3]*em1 : 0.f;
            *(unsigned*)(smem + OFF_GH + s0*PB + l0*2) = pack_hi2(v00, v01);
            *(unsigned*)(smem + OFF_GL + s0*PB + l0*2) = pack_lo2(v00, v01);
            *(unsigned*)(smem + OFF_GH + s1*PB + l0*2) = pack_hi2(v10, v11);
            *(unsigned*)(smem + OFF_GL + s1*PB + l0*2) = pack_lo2(v10, v11);
        }
    }

    // X LDG -> regs (latency hidden under phase B's MMAs)
    #pragma unroll
    for (int i = 0; i < 8; i++) {
        const int row = i*8 + ty;
        xreg[i] = *(const float4*)(X + base + (size_t)row*1024 + col4);
    }

    // ---- phase B: A=C[l][n], Bop=S'[p][n] -> accY[l][p] ----
    #pragma unroll
    for (int nt = 0; nt < 8; nt++)
        #pragma unroll
        for (int j = 0; j < 4; j++) accY[nt][j] = 0.f;
    #pragma unroll
    for (int kt = 0; kt < 4; kt++) {
        const int kb = (kt*16 + 2*t4)*2;
        ah[kt*4+0] = *(const unsigned*)(smem + OFF_CH + (r0  )*PB + kb);
        ah[kt*4+1] = *(const unsigned*)(smem + OFF_CH + (r0+8)*PB + kb);
        ah[kt*4+2] = *(const unsigned*)(smem + OFF_CH + (r0  )*PB + kb + 16);
        ah[kt*4+3] = *(const unsigned*)(smem + OFF_CH + (r0+8)*PB + kb + 16);
        al[kt*4+0] = *(const unsigned*)(smem + OFF_CL + (r0  )*PB + kb);
        al[kt*4+1] = *(const unsigned*)(smem + OFF_CL + (r0+8)*PB + kb);
        al[kt*4+2] = *(const unsigned*)(smem + OFF_CL + (r0  )*PB + kb + 16);
        al[kt*4+3] = *(const unsigned*)(smem + OFF_CL + (r0+8)*PB + kb + 16);
    }
    #pragma unroll
    for (int nt = 0; nt < 8; nt++) {
        #pragma unroll
        for (int kt = 0; kt < 4; kt++) {
            const int kb = (kt*16 + 2*t4)*2;
            const char* pr = smem + (nt*8 + gq)*PB + kb;
            unsigned bh0 = *(const unsigned*)(pr + OFF_SH);
            unsigned bh1 = *(const unsigned*)(pr + OFF_SH + 16);
            unsigned bl0 = *(const unsigned*)(pr + OFF_SL);
            unsigned bl1 = *(const unsigned*)(pr + OFF_SL + 16);
            MMA_BF16(accY[nt], ah[kt*4+0], ah[kt*4+1], ah[kt*4+2], ah[kt*4+3], bh0, bh1);
            MMA_BF16(accY[nt], ah[kt*4+0], ah[kt*4+1], ah[kt*4+2], ah[kt*4+3], bl0, bl1);
            MMA_BF16(accY[nt], al[kt*4+0], al[kt*4+1], al[kt*4+2], al[kt*4+3], bh0, bh1);
        }
    }
    __syncthreads();   // S tiles dead -> reusable for X

    // X split-store from regs (no latency)
    #pragma unroll
    for (int i = 0; i < 8; i++) {
        const int row = i*8 + ty;
        split4_store(xreg[i], smem + OFF_XH + row*PB + col4*2,
                              smem + OFF_XL + row*PB + col4*2);
    }
    __syncthreads();

    // ---- phase A: accY += G^T * X (both via LDSM.trans) ----
    #pragma unroll
    for (int kt = 0; kt < 4; kt++) {
        ldsm4_a_trans(smem + OFF_GH, kt, 16*w, lane,
                      ah[kt*4+0], ah[kt*4+1], ah[kt*4+2], ah[kt*4+3]);
        ldsm4_a_trans(smem + OFF_GL, kt, 16*w, lane,
                      al[kt*4+0], al[kt*4+1], al[kt*4+2], al[kt*4+3]);
    }
    #pragma unroll
    for (int nt = 0; nt < 8; nt++) {
        #pragma unroll
        for (int kh = 0; kh < 2; kh++) {
            unsigned bh0,bh1,bh2,bh3, bl0,bl1,bl2,bl3;
            ldsm4_b_trans(smem + OFF_XH, kh, nt, lane, bh0,bh1,bh2,bh3);
            ldsm4_b_trans(smem + OFF_XL, kh, nt, lane, bl0,bl1,bl2,bl3);
            const int k0 = (kh*2)*4, k1 = (kh*2+1)*4;
            MMA_BF16(accY[nt], ah[k0+0], ah[k0+1], ah[k0+2], ah[k0+3], bh0, bh1);
            MMA_BF16(accY[nt], ah[k0+0], ah[k0+1], ah[k0+2], ah[k0+3], bl0, bl1);
            MMA_BF16(accY[nt], al[k0+0], al[k0+1], al[k0+2], al[k0+3], bh0, bh1);
            MMA_BF16(accY[nt], ah[k1+0], ah[k1+1], ah[k1+2], ah[k1+3], bh2, bh3);
            MMA_BF16(accY[nt], ah[k1+0], ah[k1+1], ah[k1+2], ah[k1+3], bl2, bl3);
            MMA_BF16(accY[nt], al[k1+0], al[k1+1], al[k1+2], al[k1+3], bh2, bh3);
        }
    }

    // final: Y[l][p] = ecl[l] * accY
    {
        const int l0 = r0, l1 = r0 + 8;
        const float e0 = s_ecl[l0], e1 = s_ecl[l1];
        #pragma unroll
        for (int nt = 0; nt < 8; nt++) {
            const int p0 = nt*8 + 2*t4;
            *(float2*)(Y + base + (size_t)l0*1024 + p0) =
                make_float2(e0*accY[nt][0], e0*accY[nt][1]);
            *(float2*)(Y + base + (size_t)l1*1024 + p0) =
                make_float2(e1*accY[nt][2], e1*accY[nt][3]);
        }
    }
}

// ---------------------------------------------------------------------------
extern "C" void kernel_launch(void* const* d_in, const int* in_sizes, int n_in,
                              void* d_out, int out_size)
{
    const float* X = (const float*)d_in[0];
    const float* A = (const float*)d_in[1];
    const float* B = (const float*)d_in[2];
    const float* C = (const float*)d_in[3];
    float* Y = (float*)d_out;

    cudaFuncSetAttribute(gemm3_kernel,
                         cudaFuncAttributeMaxDynamicSharedMemorySize, SMEMG3);
    cudaFuncSetAttribute(pass3_kernel,
                         cudaFuncAttributeMaxDynamicSharedMemorySize, SMEM3);

    dim3 grid(NC, NH, NB);
    gemm3_kernel<<<grid, 128, SMEMG3>>>(X, A, B);
    pass2_kernel<<<dim3(8, NB*NH), 128>>>();
    pass3_kernel<<<grid, 128, SMEM3>>>(X, A, B, C, Y);
}